// round 1
// baseline (speedup 1.0000x reference)
#include <cuda_runtime.h>
#include <math.h>

#define Bx   2
#define Mx   1024
#define Vx   300
#define Cx   128
#define HIDx 128
#define BINx 256
#define Hx   384
#define Wx   512

// scratch (no cudaMalloc allowed)
__device__ float g_a[Vx * HIDx];
__device__ float g_bias[Vx];

// ---------------------------------------------------------------------------
// Kernel 1: per-view anchor MLP  a = relu(vd@Wa1+ba1)@Wa2+ba2   (V,HID)
//           bias = (relu(vd@Wb1+bb1)@Wb2+bb2)                   (V,)
// ---------------------------------------------------------------------------
__global__ void view_mlp_kernel(
    const float* __restrict__ vd,
    const float* __restrict__ Wa1, const float* __restrict__ ba1,
    const float* __restrict__ Wa2, const float* __restrict__ ba2,
    const float* __restrict__ Wb1, const float* __restrict__ bb1,
    const float* __restrict__ Wb2, const float* __restrict__ bb2)
{
    const int v = blockIdx.x;
    const int t = threadIdx.x;
    __shared__ float h1[HIDx];
    __shared__ float hb[64];

    float d0 = vd[v * 3 + 0], d1 = vd[v * 3 + 1], d2 = vd[v * 3 + 2];

    float s = ba1[t];
    s = fmaf(d0, Wa1[0 * HIDx + t], s);
    s = fmaf(d1, Wa1[1 * HIDx + t], s);
    s = fmaf(d2, Wa1[2 * HIDx + t], s);
    h1[t] = fmaxf(s, 0.0f);

    if (t < 64) {
        float sb = bb1[t];
        sb = fmaf(d0, Wb1[0 * 64 + t], sb);
        sb = fmaf(d1, Wb1[1 * 64 + t], sb);
        sb = fmaf(d2, Wb1[2 * 64 + t], sb);
        hb[t] = fmaxf(sb, 0.0f);
    }
    __syncthreads();

    float acc = ba2[t];
#pragma unroll 8
    for (int i = 0; i < HIDx; i++) acc = fmaf(h1[i], Wa2[i * HIDx + t], acc);
    g_a[v * HIDx + t] = acc;

    if (t == 0) {
        float bsum = bb2[0];
        for (int k = 0; k < 64; k++) bsum = fmaf(hb[k], Wb2[k], bsum);
        g_bias[v] = bsum;
    }
}

// ---------------------------------------------------------------------------
// Kernel 2: one block per seed (b,m). 128 threads.
// ---------------------------------------------------------------------------
__global__ void __launch_bounds__(128) seed_kernel(
    const float* __restrict__ seed_features,   // (B,C,M)
    const int*   __restrict__ token_sel_idx,   // (B,M)
    const float* __restrict__ Kmat,            // (B,3,3)
    const float* __restrict__ depth_map,       // (B,1,H,W)
    const float* __restrict__ depth_prob,      // (B,BIN,H,W)
    const float* __restrict__ vd,              // (V,3)
    const float* __restrict__ Wq1, const float* __restrict__ bq1,
    const float* __restrict__ Wq2, const float* __restrict__ bq2,
    const float* __restrict__ Wr1, const float* __restrict__ br1,
    const float* __restrict__ Wr2, const float* __restrict__ br2,
    float* __restrict__ o_score,   // (B,M,V)
    float* __restrict__ o_top,     // (B,M)
    float* __restrict__ o_xyz,     // (B,M,3)
    float* __restrict__ o_rot,     // (B,M,3,3)
    float* __restrict__ o_res)     // (B,C,M)
{
    const int bm = blockIdx.x;
    const int b  = bm / Mx;
    const int m  = bm % Mx;
    const int t  = threadIdx.x;
    const int HW = Hx * Wx;

    __shared__ __align__(16) float qin[136];
    __shared__ __align__(16) float sh1[HIDx];
    __shared__ __align__(16) float sq[HIDx];
    __shared__ __align__(16) float sh2[HIDx];
    __shared__ float wred[4];
    __shared__ float sbest[128];
    __shared__ int   sidx[128];

    const int idx = token_sel_idx[b * Mx + m];
    const float fx = Kmat[b * 9 + 0], cx = Kmat[b * 9 + 2];
    const float fy = Kmat[b * 9 + 4], cy = Kmat[b * 9 + 5];
    const int uu = idx % Wx;
    const int vv0 = idx / Wx;

    // ---- depth-entropy uncertainty at this pixel (cooperative over bins) ----
    const float* dp = depth_prob + (size_t)b * BINx * HW + idx;
    float ps = 0.0f;
    for (int k = t; k < BINx; k += 128) {
        float p = fmaxf(dp[(size_t)k * HW], 1e-8f);
        ps += p * logf(p);
    }
#pragma unroll
    for (int off = 16; off; off >>= 1) ps += __shfl_down_sync(0xffffffffu, ps, off);
    if ((t & 31) == 0) wred[t >> 5] = ps;
    __syncthreads();
    float uncert = -(wred[0] + wred[1] + wred[2] + wred[3]) * (1.0f / 5.545177444479562f); // /ln(256)
    uncert = fminf(fmaxf(uncert, 0.0f), 1.0f);

    // ---- central-difference normal at clamped interior pixel (redundant per thread) ----
    const int hc = min(max(vv0, 1), Hx - 2);
    const int wc = min(max(uu, 1), Wx - 2);
    const float* dm = depth_map + (size_t)b * HW;
    const float zL = dm[hc * Wx + wc - 1];
    const float zR = dm[hc * Wx + wc + 1];
    const float zU = dm[(hc - 1) * Wx + wc];
    const float zD = dm[(hc + 1) * Wx + wc];

    const float xL = ((float)(wc - 1) - cx) / fx;
    const float xR = ((float)(wc + 1) - cx) / fx;
    const float xC = ((float)wc       - cx) / fx;
    const float yC = ((float)hc       - cy) / fy;
    const float yU = ((float)(hc - 1) - cy) / fy;
    const float yD = ((float)(hc + 1) - cy) / fy;

    const float dxx = xR * zR - xL * zL;
    const float dxy = yC * zR - yC * zL;
    const float dxz = zR - zL;
    const float dyx = xC * zD - xC * zU;
    const float dyy = yD * zD - yU * zU;
    const float dyz = zD - zU;

    float nx = dxy * dyz - dxz * dyy;
    float ny = dxz * dyx - dxx * dyz;
    float nz = dxx * dyy - dxy * dyx;
    const float nn = fmaxf(sqrtf(nx * nx + ny * ny + nz * nz), 1e-6f);
    nx /= nn; ny /= nn; nz /= nn;

    // ---- ray ----
    const float rx = ((float)uu - cx) / fx;
    const float ry = ((float)vv0 - cy) / fy;
    const float rn = fmaxf(sqrtf(rx * rx + ry * ry + 1.0f), 1e-12f);

    // ---- build q_in (135) ----
    qin[t] = seed_features[(size_t)b * Cx * Mx + (size_t)t * Mx + m];
    if (t == 0) {
        qin[128] = rx / rn;
        qin[129] = ry / rn;
        qin[130] = 1.0f / rn;
        const float w1 = 1.0f - uncert;
        qin[131] = nx * w1;
        qin[132] = ny * w1;
        qin[133] = nz * w1;
        qin[134] = uncert;
    }
    __syncthreads();

    // ---- q MLP ----
    float acc = bq1[t];
#pragma unroll 5
    for (int i = 0; i < 135; i++) acc = fmaf(qin[i], Wq1[i * HIDx + t], acc);
    sh1[t] = fmaxf(acc, 0.0f);
    __syncthreads();

    acc = bq2[t];
#pragma unroll 8
    for (int i = 0; i < HIDx; i++) acc = fmaf(sh1[i], Wq2[i * HIDx + t], acc);
    const float qv = fmaxf(acc, 0.0f);
    sq[t] = qv;
    __syncthreads();

    // ---- logits vs all 300 views; sigmoid; local argmax ----
    const float4* q4 = (const float4*)sq;
    float best = -1.0f;
    int bestv = 0;
    const float scale = 0.0883883476483184f; // 1/sqrt(128)
    const size_t sbase = (size_t)bm * Vx;
    for (int vv = t; vv < Vx; vv += 128) {
        const float4* a4 = (const float4*)(g_a + vv * HIDx);
        float a2 = 0.0f;
#pragma unroll
        for (int h = 0; h < HIDx / 4; h++) {
            const float4 av = a4[h];
            const float4 qq = q4[h];
            a2 = fmaf(qq.x, av.x, a2);
            a2 = fmaf(qq.y, av.y, a2);
            a2 = fmaf(qq.z, av.z, a2);
            a2 = fmaf(qq.w, av.w, a2);
        }
        const float logit = a2 * scale + g_bias[vv];
        const float score = 1.0f / (1.0f + expf(-logit));
        o_score[sbase + vv] = score;
        if (score > best) { best = score; bestv = vv; }  // strict > keeps first occurrence
    }
    sbest[t] = best;
    sidx[t]  = bestv;
    __syncthreads();
    for (int s = 64; s > 0; s >>= 1) {
        if (t < s) {
            const float ob = sbest[t + s];
            const int   oi = sidx[t + s];
            if (ob > sbest[t] || (ob == sbest[t] && oi < sidx[t])) {
                sbest[t] = ob; sidx[t] = oi;
            }
        }
        __syncthreads();
    }
    const int top = sidx[0];

    // ---- per-seed scalar outputs (thread 0) ----
    if (t == 0) {
        o_top[bm] = (float)top;
        const float tvx = vd[top * 3 + 0];
        const float tvy = vd[top * 3 + 1];
        const float tvz = vd[top * 3 + 2];
        o_xyz[bm * 3 + 0] = tvx;
        o_xyz[bm * 3 + 1] = tvy;
        o_xyz[bm * 3 + 2] = tvz;

        // rot: axis_x = -v; axis_y = (-ax.y, ax.x, 0) normalized (fallback (0,1,0)); axis_z = ax x ay
        float axx = -tvx, axy = -tvy, axz = -tvz;
        float ayx = tvy,  ayy = -tvx, ayz = 0.0f;
        const float nyl = sqrtf(ayx * ayx + ayy * ayy);
        if (nyl < 1e-8f) { ayx = 0.0f; ayy = 1.0f; ayz = 0.0f; }
        else { const float inv = 1.0f / fmaxf(nyl, 1e-8f); ayx *= inv; ayy *= inv; }
        const float axn = fmaxf(sqrtf(axx * axx + axy * axy + axz * axz), 1e-8f);
        axx /= axn; axy /= axn; axz /= axn;
        const float azx = axy * ayz - axz * ayy;
        const float azy = axz * ayx - axx * ayz;
        const float azz = axx * ayy - axy * ayx;
        float* rr = o_rot + (size_t)bm * 9;
        // rot[i][j] = axis_j[i]
        rr[0] = axx; rr[1] = ayx; rr[2] = azx;
        rr[3] = axy; rr[4] = ayy; rr[5] = azy;
        rr[6] = axz; rr[7] = ayz; rr[8] = azz;
    }

    // ---- res MLP: relu((q + a_top)@Wr1 + br1)@Wr2 + br2 ----
    const float rin = qv + g_a[top * HIDx + t];
    sh1[t] = rin;           // sh1 free: last read completed before sq's __syncthreads
    __syncthreads();

    float acc3 = br1[t];
#pragma unroll 8
    for (int i = 0; i < HIDx; i++) acc3 = fmaf(sh1[i], Wr1[i * HIDx + t], acc3);
    sh2[t] = fmaxf(acc3, 0.0f);
    __syncthreads();

    float acc4 = br2[t];
#pragma unroll 8
    for (int i = 0; i < HIDx; i++) acc4 = fmaf(sh2[i], Wr2[i * HIDx + t], acc4);
    o_res[(size_t)b * Cx * Mx + (size_t)t * Mx + m] = acc4;
}

// ---------------------------------------------------------------------------
extern "C" void kernel_launch(void* const* d_in, const int* in_sizes, int n_in,
                              void* d_out, int out_size)
{
    const float* seed  = (const float*)d_in[0];
    const int*   tok   = (const int*)  d_in[1];
    const float* K     = (const float*)d_in[2];
    const float* dmap  = (const float*)d_in[3];
    const float* dprob = (const float*)d_in[4];
    const float* vd    = (const float*)d_in[5];
    const float* Wq1 = (const float*)d_in[6],  *bq1 = (const float*)d_in[7];
    const float* Wq2 = (const float*)d_in[8],  *bq2 = (const float*)d_in[9];
    const float* Wa1 = (const float*)d_in[10], *ba1 = (const float*)d_in[11];
    const float* Wa2 = (const float*)d_in[12], *ba2 = (const float*)d_in[13];
    const float* Wb1 = (const float*)d_in[14], *bb1 = (const float*)d_in[15];
    const float* Wb2 = (const float*)d_in[16], *bb2 = (const float*)d_in[17];
    const float* Wr1 = (const float*)d_in[18], *br1 = (const float*)d_in[19];
    const float* Wr2 = (const float*)d_in[20], *br2 = (const float*)d_in[21];

    float* out     = (float*)d_out;
    float* o_score = out;                          // B*M*V
    float* o_top   = o_score + (size_t)Bx * Mx * Vx;
    float* o_xyz   = o_top   + (size_t)Bx * Mx;
    float* o_rot   = o_xyz   + (size_t)Bx * Mx * 3;
    float* o_res   = o_rot   + (size_t)Bx * Mx * 9;

    view_mlp_kernel<<<Vx, 128>>>(vd, Wa1, ba1, Wa2, ba2, Wb1, bb1, Wb2, bb2);
    seed_kernel<<<Bx * Mx, 128>>>(seed, tok, K, dmap, dprob, vd,
                                  Wq1, bq1, Wq2, bq2, Wr1, br1, Wr2, br2,
                                  o_score, o_top, o_xyz, o_rot, o_res);
}

// round 2
// speedup vs baseline: 3.0901x; 3.0901x over previous
#include <cuda_runtime.h>
#include <math.h>

#define Bx   2
#define Mx   1024
#define Vx   300
#define Cx   128
#define HIDx 128
#define BINx 256
#define Hx   384
#define Wx   512
#define Sx   8          // seeds per block

__device__ float g_a[Vx * HIDx];
__device__ float g_bias[Vx];

// ---------------------------------------------------------------------------
// Kernel 1: per-view anchor MLP
// ---------------------------------------------------------------------------
__global__ void view_mlp_kernel(
    const float* __restrict__ vd,
    const float* __restrict__ Wa1, const float* __restrict__ ba1,
    const float* __restrict__ Wa2, const float* __restrict__ ba2,
    const float* __restrict__ Wb1, const float* __restrict__ bb1,
    const float* __restrict__ Wb2, const float* __restrict__ bb2)
{
    const int v = blockIdx.x;
    const int t = threadIdx.x;
    __shared__ float h1[HIDx];
    __shared__ float hb[64];

    float d0 = vd[v * 3 + 0], d1 = vd[v * 3 + 1], d2 = vd[v * 3 + 2];

    float s = ba1[t];
    s = fmaf(d0, Wa1[0 * HIDx + t], s);
    s = fmaf(d1, Wa1[1 * HIDx + t], s);
    s = fmaf(d2, Wa1[2 * HIDx + t], s);
    h1[t] = fmaxf(s, 0.0f);

    if (t < 64) {
        float sb = bb1[t];
        sb = fmaf(d0, Wb1[0 * 64 + t], sb);
        sb = fmaf(d1, Wb1[1 * 64 + t], sb);
        sb = fmaf(d2, Wb1[2 * 64 + t], sb);
        hb[t] = fmaxf(sb, 0.0f);
    }
    __syncthreads();

    float acc = ba2[t];
#pragma unroll 8
    for (int i = 0; i < HIDx; i++) acc = fmaf(h1[i], Wa2[i * HIDx + t], acc);
    g_a[v * HIDx + t] = acc;

    if (t == 0) {
        float bsum = bb2[0];
        for (int k = 0; k < 64; k++) bsum = fmaf(hb[k], Wb2[k], bsum);
        g_bias[v] = bsum;
    }
}

// ---------------------------------------------------------------------------
// Kernel 2: one block per 8 seeds. 128 threads.
// ---------------------------------------------------------------------------
__global__ void __launch_bounds__(128) seed_kernel(
    const float* __restrict__ seed_features,   // (B,C,M)
    const int*   __restrict__ token_sel_idx,   // (B,M)
    const float* __restrict__ Kmat,            // (B,3,3)
    const float* __restrict__ depth_map,       // (B,1,H,W)
    const float* __restrict__ depth_prob,      // (B,BIN,H,W)
    const float* __restrict__ vd,              // (V,3)
    const float* __restrict__ Wq1, const float* __restrict__ bq1,
    const float* __restrict__ Wq2, const float* __restrict__ bq2,
    const float* __restrict__ Wr1, const float* __restrict__ br1,
    const float* __restrict__ Wr2, const float* __restrict__ br2,
    float* __restrict__ o_score,   // (B,M,V)
    float* __restrict__ o_top,     // (B,M)
    float* __restrict__ o_xyz,     // (B,M,3)
    float* __restrict__ o_rot,     // (B,M,3,3)
    float* __restrict__ o_res)     // (B,C,M)
{
    const int bm0 = blockIdx.x * Sx;
    const int b   = bm0 / Mx;
    const int m0  = bm0 % Mx;
    const int t   = threadIdx.x;
    const int HW  = Hx * Wx;

    __shared__ __align__(16) float qin[Sx][136];
    __shared__ __align__(16) float h1[Sx][HIDx];
    __shared__ __align__(16) float qsh[Sx][HIDx];
    __shared__ __align__(16) float red[Sx][128];
    __shared__ int   redi[Sx][128];
    __shared__ float unc[Sx];
    __shared__ int   stop[Sx];

    // ---- entropy: 16 threads per seed, 16 bins each ----
    {
        const int se = t >> 4;
        const int le = t & 15;
        const int idx_e = token_sel_idx[b * Mx + m0 + se];
        const float* dp = depth_prob + (size_t)b * BINx * HW + idx_e;
        float ps = 0.0f;
#pragma unroll 4
        for (int j = 0; j < 16; j++) {
            float p = fmaxf(dp[(size_t)(le + j * 16) * HW], 1e-8f);
            ps += p * __logf(p);
        }
#pragma unroll
        for (int off = 8; off; off >>= 1) ps += __shfl_down_sync(0xffffffffu, ps, off, 16);
        if (le == 0) {
            float u = -ps * (1.0f / 5.545177444479562f); // /ln(256)
            unc[se] = fminf(fmaxf(u, 0.0f), 1.0f);
        }
    }

    // ---- seed features into qin (coalesced: 8 seeds contiguous in m) ----
    {
        const int sf = t & 7;
        const int cb = t >> 3;
        const float* sp = seed_features + (size_t)b * Cx * Mx + m0 + sf;
#pragma unroll
        for (int j = 0; j < 8; j++) {
            const int c = cb + 16 * j;
            qin[sf][c] = sp[(size_t)c * Mx];
        }
    }
    __syncthreads();

    // ---- geometry: thread s handles seed s ----
    if (t < Sx) {
        const int idx = token_sel_idx[b * Mx + m0 + t];
        const float fx = Kmat[b * 9 + 0], cx = Kmat[b * 9 + 2];
        const float fy = Kmat[b * 9 + 4], cy = Kmat[b * 9 + 5];
        const int uu  = idx % Wx;
        const int vv0 = idx / Wx;

        const int hc = min(max(vv0, 1), Hx - 2);
        const int wc = min(max(uu, 1), Wx - 2);
        const float* dm = depth_map + (size_t)b * HW;
        const float zL = dm[hc * Wx + wc - 1];
        const float zR = dm[hc * Wx + wc + 1];
        const float zU = dm[(hc - 1) * Wx + wc];
        const float zD = dm[(hc + 1) * Wx + wc];

        const float xL = ((float)(wc - 1) - cx) / fx;
        const float xR = ((float)(wc + 1) - cx) / fx;
        const float xC = ((float)wc       - cx) / fx;
        const float yC = ((float)hc       - cy) / fy;
        const float yU = ((float)(hc - 1) - cy) / fy;
        const float yD = ((float)(hc + 1) - cy) / fy;

        const float dxx = xR * zR - xL * zL;
        const float dxy = yC * zR - yC * zL;
        const float dxz = zR - zL;
        const float dyx = xC * zD - xC * zU;
        const float dyy = yD * zD - yU * zU;
        const float dyz = zD - zU;

        float nx = dxy * dyz - dxz * dyy;
        float ny = dxz * dyx - dxx * dyz;
        float nz = dxx * dyy - dxy * dyx;
        const float nn = fmaxf(sqrtf(nx * nx + ny * ny + nz * nz), 1e-6f);
        nx /= nn; ny /= nn; nz /= nn;

        const float rx = ((float)uu - cx) / fx;
        const float ry = ((float)vv0 - cy) / fy;
        const float rn = fmaxf(sqrtf(rx * rx + ry * ry + 1.0f), 1e-12f);

        const float u1 = unc[t];
        const float w1 = 1.0f - u1;
        qin[t][128] = rx / rn;
        qin[t][129] = ry / rn;
        qin[t][130] = 1.0f / rn;
        qin[t][131] = nx * w1;
        qin[t][132] = ny * w1;
        qin[t][133] = nz * w1;
        qin[t][134] = u1;
    }
    __syncthreads();

    float acc[Sx];

    // ---- q layer 1: (135 -> 128), 8 seeds batched ----
    {
        const float bv = bq1[t];
#pragma unroll
        for (int s = 0; s < Sx; s++) acc[s] = bv;
        for (int i = 0; i < 132; i += 4) {
            const float w0 = Wq1[(i + 0) * HIDx + t];
            const float w1w = Wq1[(i + 1) * HIDx + t];
            const float w2 = Wq1[(i + 2) * HIDx + t];
            const float w3 = Wq1[(i + 3) * HIDx + t];
#pragma unroll
            for (int s = 0; s < Sx; s++) {
                const float4 x = *(const float4*)&qin[s][i];
                acc[s] = fmaf(x.x, w0, acc[s]);
                acc[s] = fmaf(x.y, w1w, acc[s]);
                acc[s] = fmaf(x.z, w2, acc[s]);
                acc[s] = fmaf(x.w, w3, acc[s]);
            }
        }
#pragma unroll
        for (int i = 132; i < 135; i++) {
            const float w = Wq1[i * HIDx + t];
#pragma unroll
            for (int s = 0; s < Sx; s++) acc[s] = fmaf(qin[s][i], w, acc[s]);
        }
#pragma unroll
        for (int s = 0; s < Sx; s++) h1[s][t] = fmaxf(acc[s], 0.0f);
    }
    __syncthreads();

    // ---- q layer 2: (128 -> 128) ----
    float qv[Sx];
    {
        const float bv = bq2[t];
#pragma unroll
        for (int s = 0; s < Sx; s++) acc[s] = bv;
        for (int i = 0; i < HIDx; i += 4) {
            const float w0 = Wq2[(i + 0) * HIDx + t];
            const float w1w = Wq2[(i + 1) * HIDx + t];
            const float w2 = Wq2[(i + 2) * HIDx + t];
            const float w3 = Wq2[(i + 3) * HIDx + t];
#pragma unroll
            for (int s = 0; s < Sx; s++) {
                const float4 x = *(const float4*)&h1[s][i];
                acc[s] = fmaf(x.x, w0, acc[s]);
                acc[s] = fmaf(x.y, w1w, acc[s]);
                acc[s] = fmaf(x.z, w2, acc[s]);
                acc[s] = fmaf(x.w, w3, acc[s]);
            }
        }
#pragma unroll
        for (int s = 0; s < Sx; s++) {
            qv[s] = fmaxf(acc[s], 0.0f);
            qsh[s][t] = qv[s];
        }
    }
    __syncthreads();

    // ---- logits vs 300 views, argmax on logit (sigmoid is monotonic) ----
    {
        float best[Sx];
        int   besti[Sx];
#pragma unroll
        for (int s = 0; s < Sx; s++) { best[s] = -1e30f; besti[s] = 0; }
        const float scale = 0.0883883476483184f; // 1/sqrt(128)

        for (int vv = t; vv < Vx; vv += 128) {
            const float4* a4 = (const float4*)(g_a + vv * HIDx);
            float lg[Sx];
#pragma unroll
            for (int s = 0; s < Sx; s++) lg[s] = 0.0f;
#pragma unroll 8
            for (int h = 0; h < HIDx / 4; h++) {
                const float4 av = a4[h];
#pragma unroll
                for (int s = 0; s < Sx; s++) {
                    const float4 qq = *(const float4*)&qsh[s][4 * h];
                    lg[s] = fmaf(qq.x, av.x, lg[s]);
                    lg[s] = fmaf(qq.y, av.y, lg[s]);
                    lg[s] = fmaf(qq.z, av.z, lg[s]);
                    lg[s] = fmaf(qq.w, av.w, lg[s]);
                }
            }
            const float bvv = g_bias[vv];
#pragma unroll
            for (int s = 0; s < Sx; s++) {
                const float logit = fmaf(lg[s], scale, bvv);
                o_score[(size_t)(bm0 + s) * Vx + vv] = 1.0f / (1.0f + __expf(-logit));
                if (logit > best[s]) { best[s] = logit; besti[s] = vv; }
            }
        }
#pragma unroll
        for (int s = 0; s < Sx; s++) { red[s][t] = best[s]; redi[s][t] = besti[s]; }
    }
    __syncthreads();

    // ---- per-seed argmax reduce: warp w handles seeds 2w, 2w+1 ----
    {
        const int w = t >> 5, l = t & 31;
#pragma unroll
        for (int k = 0; k < 2; k++) {
            const int s = w * 2 + k;
            float bv = red[s][l]; int bi = redi[s][l];
#pragma unroll
            for (int o = 32; o < 128; o += 32) {
                const float ov = red[s][l + o]; const int oi = redi[s][l + o];
                if (ov > bv || (ov == bv && oi < bi)) { bv = ov; bi = oi; }
            }
#pragma unroll
            for (int off = 16; off; off >>= 1) {
                const float ov = __shfl_down_sync(0xffffffffu, bv, off);
                const int   oi = __shfl_down_sync(0xffffffffu, bi, off);
                if (ov > bv || (ov == bv && oi < bi)) { bv = ov; bi = oi; }
            }
            if (l == 0) stop[s] = bi;
        }
    }
    __syncthreads();

    // ---- per-seed scalar outputs ----
    if (t < Sx) {
        const int top = stop[t];
        const int bm = bm0 + t;
        o_top[bm] = (float)top;
        const float tvx = vd[top * 3 + 0];
        const float tvy = vd[top * 3 + 1];
        const float tvz = vd[top * 3 + 2];
        o_xyz[bm * 3 + 0] = tvx;
        o_xyz[bm * 3 + 1] = tvy;
        o_xyz[bm * 3 + 2] = tvz;

        float axx = -tvx, axy = -tvy, axz = -tvz;
        float ayx = tvy,  ayy = -tvx, ayz = 0.0f;
        const float nyl = sqrtf(ayx * ayx + ayy * ayy);
        if (nyl < 1e-8f) { ayx = 0.0f; ayy = 1.0f; ayz = 0.0f; }
        else { const float inv = 1.0f / fmaxf(nyl, 1e-8f); ayx *= inv; ayy *= inv; }
        const float axn = fmaxf(sqrtf(axx * axx + axy * axy + axz * axz), 1e-8f);
        axx /= axn; axy /= axn; axz /= axn;
        const float azx = axy * ayz - axz * ayy;
        const float azy = axz * ayx - axx * ayz;
        const float azz = axx * ayy - axy * ayx;
        float* rr = o_rot + (size_t)bm * 9;
        rr[0] = axx; rr[1] = ayx; rr[2] = azx;
        rr[3] = axy; rr[4] = ayy; rr[5] = azy;
        rr[6] = axz; rr[7] = ayz; rr[8] = azz;
    }

    // ---- res MLP input: q + a_top, into h1 (reused) ----
#pragma unroll
    for (int s = 0; s < Sx; s++) h1[s][t] = qv[s] + g_a[stop[s] * HIDx + t];
    __syncthreads();

    // ---- res layer 1 -> qsh (reused) ----
    {
        const float bv = br1[t];
#pragma unroll
        for (int s = 0; s < Sx; s++) acc[s] = bv;
        for (int i = 0; i < HIDx; i += 4) {
            const float w0 = Wr1[(i + 0) * HIDx + t];
            const float w1w = Wr1[(i + 1) * HIDx + t];
            const float w2 = Wr1[(i + 2) * HIDx + t];
            const float w3 = Wr1[(i + 3) * HIDx + t];
#pragma unroll
            for (int s = 0; s < Sx; s++) {
                const float4 x = *(const float4*)&h1[s][i];
                acc[s] = fmaf(x.x, w0, acc[s]);
                acc[s] = fmaf(x.y, w1w, acc[s]);
                acc[s] = fmaf(x.z, w2, acc[s]);
                acc[s] = fmaf(x.w, w3, acc[s]);
            }
        }
#pragma unroll
        for (int s = 0; s < Sx; s++) qsh[s][t] = fmaxf(acc[s], 0.0f);
    }
    __syncthreads();

    // ---- res layer 2 -> output ----
    {
        const float bv = br2[t];
#pragma unroll
        for (int s = 0; s < Sx; s++) acc[s] = bv;
        for (int i = 0; i < HIDx; i += 4) {
            const float w0 = Wr2[(i + 0) * HIDx + t];
            const float w1w = Wr2[(i + 1) * HIDx + t];
            const float w2 = Wr2[(i + 2) * HIDx + t];
            const float w3 = Wr2[(i + 3) * HIDx + t];
#pragma unroll
            for (int s = 0; s < Sx; s++) {
                const float4 x = *(const float4*)&qsh[s][i];
                acc[s] = fmaf(x.x, w0, acc[s]);
                acc[s] = fmaf(x.y, w1w, acc[s]);
                acc[s] = fmaf(x.z, w2, acc[s]);
                acc[s] = fmaf(x.w, w3, acc[s]);
            }
        }
        float* op = o_res + (size_t)b * Cx * Mx + (size_t)t * Mx + m0;
#pragma unroll
        for (int s = 0; s < Sx; s++) op[s] = acc[s];
    }
}

// ---------------------------------------------------------------------------
extern "C" void kernel_launch(void* const* d_in, const int* in_sizes, int n_in,
                              void* d_out, int out_size)
{
    const float* seed  = (const float*)d_in[0];
    const int*   tok   = (const int*)  d_in[1];
    const float* K     = (const float*)d_in[2];
    const float* dmap  = (const float*)d_in[3];
    const float* dprob = (const float*)d_in[4];
    const float* vd    = (const float*)d_in[5];
    const float* Wq1 = (const float*)d_in[6],  *bq1 = (const float*)d_in[7];
    const float* Wq2 = (const float*)d_in[8],  *bq2 = (const float*)d_in[9];
    const float* Wa1 = (const float*)d_in[10], *ba1 = (const float*)d_in[11];
    const float* Wa2 = (const float*)d_in[12], *ba2 = (const float*)d_in[13];
    const float* Wb1 = (const float*)d_in[14], *bb1 = (const float*)d_in[15];
    const float* Wb2 = (const float*)d_in[16], *bb2 = (const float*)d_in[17];
    const float* Wr1 = (const float*)d_in[18], *br1 = (const float*)d_in[19];
    const float* Wr2 = (const float*)d_in[20], *br2 = (const float*)d_in[21];

    float* out     = (float*)d_out;
    float* o_score = out;
    float* o_top   = o_score + (size_t)Bx * Mx * Vx;
    float* o_xyz   = o_top   + (size_t)Bx * Mx;
    float* o_rot   = o_xyz   + (size_t)Bx * Mx * 3;
    float* o_res   = o_rot   + (size_t)Bx * Mx * 9;

    view_mlp_kernel<<<Vx, 128>>>(vd, Wa1, ba1, Wa2, ba2, Wb1, bb1, Wb2, bb2);
    seed_kernel<<<(Bx * Mx) / Sx, 128>>>(seed, tok, K, dmap, dprob, vd,
                                         Wq1, bq1, Wq2, bq2, Wr1, br1, Wr2, br2,
                                         o_score, o_top, o_xyz, o_rot, o_res);
}

// round 3
// speedup vs baseline: 3.3731x; 1.0916x over previous
#include <cuda_runtime.h>
#include <math.h>

#define Bx   2
#define Mx   1024
#define Vx   300
#define Cx   128
#define HIDx 128
#define BINx 256
#define Hx   384
#define Wx   512
#define Sx   8          // seeds per block

__device__ float g_a[Vx * HIDx];
__device__ float g_bias[Vx];

// ---------------------------------------------------------------------------
// Kernel 1: per-view anchor MLP
// ---------------------------------------------------------------------------
__global__ void view_mlp_kernel(
    const float* __restrict__ vd,
    const float* __restrict__ Wa1, const float* __restrict__ ba1,
    const float* __restrict__ Wa2, const float* __restrict__ ba2,
    const float* __restrict__ Wb1, const float* __restrict__ bb1,
    const float* __restrict__ Wb2, const float* __restrict__ bb2)
{
    const int v = blockIdx.x;
    const int t = threadIdx.x;
    __shared__ float h1[HIDx];
    __shared__ float hb[64];

    float d0 = vd[v * 3 + 0], d1 = vd[v * 3 + 1], d2 = vd[v * 3 + 2];

    float s = ba1[t];
    s = fmaf(d0, Wa1[0 * HIDx + t], s);
    s = fmaf(d1, Wa1[1 * HIDx + t], s);
    s = fmaf(d2, Wa1[2 * HIDx + t], s);
    h1[t] = fmaxf(s, 0.0f);

    if (t < 64) {
        float sb = bb1[t];
        sb = fmaf(d0, Wb1[0 * 64 + t], sb);
        sb = fmaf(d1, Wb1[1 * 64 + t], sb);
        sb = fmaf(d2, Wb1[2 * 64 + t], sb);
        hb[t] = fmaxf(sb, 0.0f);
    }
    __syncthreads();

    float acc = ba2[t];
#pragma unroll 8
    for (int i = 0; i < HIDx; i++) acc = fmaf(h1[i], Wa2[i * HIDx + t], acc);
    g_a[v * HIDx + t] = acc;

    if (t == 0) {
        float bsum = bb2[0];
        for (int k = 0; k < 64; k++) bsum = fmaf(hb[k], Wb2[k], bsum);
        g_bias[v] = bsum;
    }
}

// ---------------------------------------------------------------------------
// Kernel 2: 8 seeds per block, 256 threads (K-split halves for MLP layers).
// ---------------------------------------------------------------------------
__global__ void __launch_bounds__(256) seed_kernel(
    const float* __restrict__ seed_features,   // (B,C,M)
    const int*   __restrict__ token_sel_idx,   // (B,M)
    const float* __restrict__ Kmat,            // (B,3,3)
    const float* __restrict__ depth_map,       // (B,1,H,W)
    const float* __restrict__ depth_prob,      // (B,BIN,H,W)
    const float* __restrict__ vd,              // (V,3)
    const float* __restrict__ Wq1, const float* __restrict__ bq1,
    const float* __restrict__ Wq2, const float* __restrict__ bq2,
    const float* __restrict__ Wr1, const float* __restrict__ br1,
    const float* __restrict__ Wr2, const float* __restrict__ br2,
    float* __restrict__ o_score,   // (B,M,V)
    float* __restrict__ o_top,     // (B,M)
    float* __restrict__ o_xyz,     // (B,M,3)
    float* __restrict__ o_rot,     // (B,M,3,3)
    float* __restrict__ o_res)     // (B,C,M)
{
    const int bm0 = blockIdx.x * Sx;
    const int b   = bm0 / Mx;
    const int m0  = bm0 % Mx;
    const int t   = threadIdx.x;
    const int tt  = t & 127;     // output neuron
    const int half = t >> 7;     // K half
    const int HW  = Hx * Wx;

    __shared__ __align__(16) float qin[Sx][136];
    __shared__ __align__(16) float h1[Sx][HIDx];
    __shared__ __align__(16) float qsh[Sx][HIDx];
    __shared__ __align__(16) float part[Sx][HIDx];
    __shared__ float wbest[Sx][8];
    __shared__ int   wbesti[Sx][8];
    __shared__ float unc[Sx];
    __shared__ int   stop[Sx];

    // ---- entropy: 32 threads per seed, 8 bins each ----
    {
        const int se = t >> 5;
        const int le = t & 31;
        const int idx_e = token_sel_idx[b * Mx + m0 + se];
        const float* dp = depth_prob + (size_t)b * BINx * HW + idx_e;
        float ps = 0.0f;
#pragma unroll
        for (int j = 0; j < 8; j++) {
            float p = fmaxf(dp[(size_t)(le + j * 32) * HW], 1e-8f);
            ps += p * __logf(p);
        }
#pragma unroll
        for (int off = 16; off; off >>= 1) ps += __shfl_down_sync(0xffffffffu, ps, off);
        if (le == 0) {
            float u = -ps * (1.0f / 5.545177444479562f); // /ln(256)
            unc[se] = fminf(fmaxf(u, 0.0f), 1.0f);
        }
    }

    // ---- seed features into qin (coalesced) ----
    {
        const int sf = t & 7;
        const int cb = t >> 3;               // 0..31
        const float* sp = seed_features + (size_t)b * Cx * Mx + m0 + sf;
#pragma unroll
        for (int j = 0; j < 4; j++) {
            const int c = cb + 32 * j;
            qin[sf][c] = sp[(size_t)c * Mx];
        }
    }
    __syncthreads();

    // ---- geometry: thread s handles seed s ----
    if (t < Sx) {
        const int idx = token_sel_idx[b * Mx + m0 + t];
        const float fx = Kmat[b * 9 + 0], cx = Kmat[b * 9 + 2];
        const float fy = Kmat[b * 9 + 4], cy = Kmat[b * 9 + 5];
        const int uu  = idx % Wx;
        const int vv0 = idx / Wx;

        const int hc = min(max(vv0, 1), Hx - 2);
        const int wc = min(max(uu, 1), Wx - 2);
        const float* dm = depth_map + (size_t)b * HW;
        const float zL = dm[hc * Wx + wc - 1];
        const float zR = dm[hc * Wx + wc + 1];
        const float zU = dm[(hc - 1) * Wx + wc];
        const float zD = dm[(hc + 1) * Wx + wc];

        const float xL = ((float)(wc - 1) - cx) / fx;
        const float xR = ((float)(wc + 1) - cx) / fx;
        const float xC = ((float)wc       - cx) / fx;
        const float yC = ((float)hc       - cy) / fy;
        const float yU = ((float)(hc - 1) - cy) / fy;
        const float yD = ((float)(hc + 1) - cy) / fy;

        const float dxx = xR * zR - xL * zL;
        const float dxy = yC * zR - yC * zL;
        const float dxz = zR - zL;
        const float dyx = xC * zD - xC * zU;
        const float dyy = yD * zD - yU * zU;
        const float dyz = zD - zU;

        float nx = dxy * dyz - dxz * dyy;
        float ny = dxz * dyx - dxx * dyz;
        float nz = dxx * dyy - dxy * dyx;
        const float nn = fmaxf(sqrtf(nx * nx + ny * ny + nz * nz), 1e-6f);
        nx /= nn; ny /= nn; nz /= nn;

        const float rx = ((float)uu - cx) / fx;
        const float ry = ((float)vv0 - cy) / fy;
        const float rn = fmaxf(sqrtf(rx * rx + ry * ry + 1.0f), 1e-12f);

        const float u1 = unc[t];
        const float w1 = 1.0f - u1;
        qin[t][128] = rx / rn;
        qin[t][129] = ry / rn;
        qin[t][130] = 1.0f / rn;
        qin[t][131] = nx * w1;
        qin[t][132] = ny * w1;
        qin[t][133] = nz * w1;
        qin[t][134] = u1;
    }
    __syncthreads();

    float acc[Sx];

    // ================= q layer 1 (135 -> 128), K-split 0..67 / 68..134 =====
    {
#pragma unroll
        for (int s = 0; s < Sx; s++) acc[s] = 0.0f;
        const int i0 = half ? 68 : 0;
        const int i1 = half ? 132 : 68;
        for (int i = i0; i < i1; i += 4) {
            const float w0 = Wq1[(i + 0) * HIDx + tt];
            const float w1w = Wq1[(i + 1) * HIDx + tt];
            const float w2 = Wq1[(i + 2) * HIDx + tt];
            const float w3 = Wq1[(i + 3) * HIDx + tt];
#pragma unroll
            for (int s = 0; s < Sx; s++) {
                const float4 x = *(const float4*)&qin[s][i];
                acc[s] = fmaf(x.x, w0, acc[s]);
                acc[s] = fmaf(x.y, w1w, acc[s]);
                acc[s] = fmaf(x.z, w2, acc[s]);
                acc[s] = fmaf(x.w, w3, acc[s]);
            }
        }
        if (half) {
#pragma unroll
            for (int i = 132; i < 135; i++) {
                const float w = Wq1[i * HIDx + tt];
#pragma unroll
                for (int s = 0; s < Sx; s++) acc[s] = fmaf(qin[s][i], w, acc[s]);
            }
#pragma unroll
            for (int s = 0; s < Sx; s++) part[s][tt] = acc[s];
        }
        __syncthreads();
        if (!half) {
            const float bv = bq1[tt];
#pragma unroll
            for (int s = 0; s < Sx; s++)
                h1[s][tt] = fmaxf(acc[s] + part[s][tt] + bv, 0.0f);
        }
        __syncthreads();
    }

    // ================= q layer 2 (128 -> 128) ==============================
    {
#pragma unroll
        for (int s = 0; s < Sx; s++) acc[s] = 0.0f;
        const int i0 = half * 64;
        for (int i = i0; i < i0 + 64; i += 4) {
            const float w0 = Wq2[(i + 0) * HIDx + tt];
            const float w1w = Wq2[(i + 1) * HIDx + tt];
            const float w2 = Wq2[(i + 2) * HIDx + tt];
            const float w3 = Wq2[(i + 3) * HIDx + tt];
#pragma unroll
            for (int s = 0; s < Sx; s++) {
                const float4 x = *(const float4*)&h1[s][i];
                acc[s] = fmaf(x.x, w0, acc[s]);
                acc[s] = fmaf(x.y, w1w, acc[s]);
                acc[s] = fmaf(x.z, w2, acc[s]);
                acc[s] = fmaf(x.w, w3, acc[s]);
            }
        }
        if (half) {
#pragma unroll
            for (int s = 0; s < Sx; s++) part[s][tt] = acc[s];
        }
        __syncthreads();
        if (!half) {
            const float bv = bq2[tt];
#pragma unroll
            for (int s = 0; s < Sx; s++)
                qsh[s][tt] = fmaxf(acc[s] + part[s][tt] + bv, 0.0f);
        }
        __syncthreads();
    }

    // ================= logits vs 300 views (256 threads over views) ========
    {
        float best[Sx];
        int   besti[Sx];
#pragma unroll
        for (int s = 0; s < Sx; s++) { best[s] = -1e30f; besti[s] = 0; }
        const float scale = 0.0883883476483184f; // 1/sqrt(128)

        for (int vv = t; vv < Vx; vv += 256) {
            const float4* a4 = (const float4*)(g_a + vv * HIDx);
            float lg[Sx];
#pragma unroll
            for (int s = 0; s < Sx; s++) lg[s] = 0.0f;
#pragma unroll 8
            for (int h = 0; h < HIDx / 4; h++) {
                const float4 av = a4[h];
#pragma unroll
                for (int s = 0; s < Sx; s++) {
                    const float4 qq = *(const float4*)&qsh[s][4 * h];
                    lg[s] = fmaf(qq.x, av.x, lg[s]);
                    lg[s] = fmaf(qq.y, av.y, lg[s]);
                    lg[s] = fmaf(qq.z, av.z, lg[s]);
                    lg[s] = fmaf(qq.w, av.w, lg[s]);
                }
            }
            const float bvv = g_bias[vv];
#pragma unroll
            for (int s = 0; s < Sx; s++) {
                const float logit = fmaf(lg[s], scale, bvv);
                o_score[(size_t)(bm0 + s) * Vx + vv] = 1.0f / (1.0f + __expf(-logit));
                if (logit > best[s]) { best[s] = logit; besti[s] = vv; }
            }
        }

        // warp-level argmax reduce
        const int w = t >> 5, l = t & 31;
#pragma unroll
        for (int s = 0; s < Sx; s++) {
            float bv = best[s]; int bi = besti[s];
#pragma unroll
            for (int off = 16; off; off >>= 1) {
                const float ov = __shfl_down_sync(0xffffffffu, bv, off);
                const int   oi = __shfl_down_sync(0xffffffffu, bi, off);
                if (ov > bv || (ov == bv && oi < bi)) { bv = ov; bi = oi; }
            }
            if (l == 0) { wbest[s][w] = bv; wbesti[s][w] = bi; }
        }
    }
    __syncthreads();

    // ---- cross-warp argmax: threads 0..63, group of 8 per seed ----
    if (t < 64) {
        const int s = t >> 3, l = t & 7;
        float bv = wbest[s][l]; int bi = wbesti[s][l];
#pragma unroll
        for (int off = 4; off; off >>= 1) {
            const float ov = __shfl_down_sync(0xffffffffu, bv, off, 8);
            const int   oi = __shfl_down_sync(0xffffffffu, bi, off, 8);
            if (ov > bv || (ov == bv && oi < bi)) { bv = ov; bi = oi; }
        }
        if (l == 0) stop[s] = bi;
    }
    __syncthreads();

    // ---- per-seed scalar outputs ----
    if (t < Sx) {
        const int top = stop[t];
        const int bm = bm0 + t;
        o_top[bm] = (float)top;
        const float tvx = vd[top * 3 + 0];
        const float tvy = vd[top * 3 + 1];
        const float tvz = vd[top * 3 + 2];
        o_xyz[bm * 3 + 0] = tvx;
        o_xyz[bm * 3 + 1] = tvy;
        o_xyz[bm * 3 + 2] = tvz;

        float axx = -tvx, axy = -tvy, axz = -tvz;
        float ayx = tvy,  ayy = -tvx, ayz = 0.0f;
        const float nyl = sqrtf(ayx * ayx + ayy * ayy);
        if (nyl < 1e-8f) { ayx = 0.0f; ayy = 1.0f; ayz = 0.0f; }
        else { const float inv = 1.0f / fmaxf(nyl, 1e-8f); ayx *= inv; ayy *= inv; }
        const float axn = fmaxf(sqrtf(axx * axx + axy * axy + axz * axz), 1e-8f);
        axx /= axn; axy /= axn; axz /= axn;
        const float azx = axy * ayz - axz * ayy;
        const float azy = axz * ayx - axx * ayz;
        const float azz = axx * ayy - axy * ayx;
        float* rr = o_rot + (size_t)bm * 9;
        rr[0] = axx; rr[1] = ayx; rr[2] = azx;
        rr[3] = axy; rr[4] = ayy; rr[5] = azy;
        rr[6] = axz; rr[7] = ayz; rr[8] = azz;
    }

    // ---- res input: q + a_top -> h1 (written by half0) ----
    if (!half) {
#pragma unroll
        for (int s = 0; s < Sx; s++)
            h1[s][tt] = qsh[s][tt] + g_a[stop[s] * HIDx + tt];
    }
    __syncthreads();

    // ================= res layer 1 (128 -> 128) -> qin (reused) ============
    {
#pragma unroll
        for (int s = 0; s < Sx; s++) acc[s] = 0.0f;
        const int i0 = half * 64;
        for (int i = i0; i < i0 + 64; i += 4) {
            const float w0 = Wr1[(i + 0) * HIDx + tt];
            const float w1w = Wr1[(i + 1) * HIDx + tt];
            const float w2 = Wr1[(i + 2) * HIDx + tt];
            const float w3 = Wr1[(i + 3) * HIDx + tt];
#pragma unroll
            for (int s = 0; s < Sx; s++) {
                const float4 x = *(const float4*)&h1[s][i];
                acc[s] = fmaf(x.x, w0, acc[s]);
                acc[s] = fmaf(x.y, w1w, acc[s]);
                acc[s] = fmaf(x.z, w2, acc[s]);
                acc[s] = fmaf(x.w, w3, acc[s]);
            }
        }
        if (half) {
#pragma unroll
            for (int s = 0; s < Sx; s++) part[s][tt] = acc[s];
        }
        __syncthreads();
        if (!half) {
            const float bv = br1[tt];
#pragma unroll
            for (int s = 0; s < Sx; s++)
                qin[s][tt] = fmaxf(acc[s] + part[s][tt] + bv, 0.0f);
        }
        __syncthreads();
    }

    // ================= res layer 2 (128 -> 128) -> output ==================
    {
#pragma unroll
        for (int s = 0; s < Sx; s++) acc[s] = 0.0f;
        const int i0 = half * 64;
        for (int i = i0; i < i0 + 64; i += 4) {
            const float w0 = Wr2[(i + 0) * HIDx + tt];
            const float w1w = Wr2[(i + 1) * HIDx + tt];
            const float w2 = Wr2[(i + 2) * HIDx + tt];
            const float w3 = Wr2[(i + 3) * HIDx + tt];
#pragma unroll
            for (int s = 0; s < Sx; s++) {
                const float4 x = *(const float4*)&qin[s][i];
                acc[s] = fmaf(x.x, w0, acc[s]);
                acc[s] = fmaf(x.y, w1w, acc[s]);
                acc[s] = fmaf(x.z, w2, acc[s]);
                acc[s] = fmaf(x.w, w3, acc[s]);
            }
        }
        if (half) {
#pragma unroll
            for (int s = 0; s < Sx; s++) part[s][tt] = acc[s];
        }
        __syncthreads();
        if (!half) {
            const float bv = br2[tt];
            float* op = o_res + (size_t)b * Cx * Mx + (size_t)tt * Mx + m0;
#pragma unroll
            for (int s = 0; s < Sx; s++)
                op[s] = acc[s] + part[s][tt] + bv;
        }
    }
}

// ---------------------------------------------------------------------------
extern "C" void kernel_launch(void* const* d_in, const int* in_sizes, int n_in,
                              void* d_out, int out_size)
{
    const float* seed  = (const float*)d_in[0];
    const int*   tok   = (const int*)  d_in[1];
    const float* K     = (const float*)d_in[2];
    const float* dmap  = (const float*)d_in[3];
    const float* dprob = (const float*)d_in[4];
    const float* vd    = (const float*)d_in[5];
    const float* Wq1 = (const float*)d_in[6],  *bq1 = (const float*)d_in[7];
    const float* Wq2 = (const float*)d_in[8],  *bq2 = (const float*)d_in[9];
    const float* Wa1 = (const float*)d_in[10], *ba1 = (const float*)d_in[11];
    const float* Wa2 = (const float*)d_in[12], *ba2 = (const float*)d_in[13];
    const float* Wb1 = (const float*)d_in[14], *bb1 = (const float*)d_in[15];
    const float* Wb2 = (const float*)d_in[16], *bb2 = (const float*)d_in[17];
    const float* Wr1 = (const float*)d_in[18], *br1 = (const float*)d_in[19];
    const float* Wr2 = (const float*)d_in[20], *br2 = (const float*)d_in[21];

    float* out     = (float*)d_out;
    float* o_score = out;
    float* o_top   = o_score + (size_t)Bx * Mx * Vx;
    float* o_xyz   = o_top   + (size_t)Bx * Mx;
    float* o_rot   = o_xyz   + (size_t)Bx * Mx * 3;
    float* o_res   = o_rot   + (size_t)Bx * Mx * 9;

    view_mlp_kernel<<<Vx, 128>>>(vd, Wa1, ba1, Wa2, ba2, Wb1, bb1, Wb2, bb2);
    seed_kernel<<<(Bx * Mx) / Sx, 256>>>(seed, tok, K, dmap, dprob, vd,
                                         Wq1, bq1, Wq2, bq2, Wr1, br1, Wr2, br2,
                                         o_score, o_top, o_xyz, o_rot, o_res);
}